// round 17
// baseline (speedup 1.0000x reference)
#include <cuda_runtime.h>
#include <cuda_bf16.h>

// Output: [Cm1, 1, R, 85] fp32 flat (NC = 81).
//
// Dense 2-class kernel. Group = 4 rows = 340 elems = 85 float4s.
// Boundary float4 positions in a group: {20,21,41,42,62,63,84}.
// Block owns 8 groups = 680 contiguous float4s for TWO class planes (c0, c1):
//   Phase 1: R16's dense loop for plane c0, stashing each float4 + position.
//   Phase 2: replay stash to plane c1 (fast: 1 STG; boundary: redo box math
//            with regr[r, c1], reusing stashed cls-blend values).
// Halves cls L2 read traffic (the LTS cap is the measured wall) while keeping
// the proven dense per-plane store topology, phase-sequenced not interleaved.

__global__ void __launch_bounds__(256)
bb_dense2_kernel(const float* __restrict__ cls,     // [R, 81]
                 const float4* __restrict__ cls4,
                 const float4* __restrict__ regr4,  // [R, Cm1] of float4
                 const float4* __restrict__ rois,   // [R] of float4
                 float4* __restrict__ out4,
                 int perC4,        // 85*R/4
                 int R, int Cm1,
                 float invW, float invH)
{
    const int c0 = blockIdx.y * 2;
    const int c1 = c0 + 1;
    const bool c1ok = (c1 < Cm1);
    float4* plane0 = out4 + (size_t)c0 * (size_t)perC4;
    float4* plane1 = plane0 + perC4;

    const int gbase = blockIdx.x * 8;        // first group of this block
    const int tbase = blockIdx.x * 680;      // first plane float4 of this block

    float4 val[3];                           // stashed payload (cls or clsv-blend)
    int    locs[3];                          // block-local pos; sign bit = boundary

    // ---------------- Phase 1: plane c0 (dense, write-every-float4) ----------------
#pragma unroll
    for (int s = 0; s < 3; ++s) {
        int v = threadIdx.x + s * 256;
        locs[s] = -2147483647 - 1;           // sentinel: no task (store 0x80000000)
        if (v >= 680) continue;

        if (v < 624) {
            // ---------- FAST: pure cls copy ----------
            unsigned w  = (unsigned)v % 78u;
            unsigned gg = (unsigned)v / 78u;
            unsigned cnt = (w >= 20u) + (w >= 39u) + (w >= 58u);
            int loc = (int)(85u * gg + w + 2u * cnt);
            int idx = (int)(81u * (unsigned)(gbase + (int)gg) + w + cnt);
            float4 x = __ldg(&cls4[idx]);
            __stcs(&plane0[tbase + loc], x);
            val[s]  = x;
            locs[s] = loc;                   // >= 0 => fast
        } else {
            // ---------- BOUNDARY: box math + cls blend ----------
            unsigned ub = (unsigned)(v - 624);
            unsigned q  = ub % 7u;
            unsigned gg = ub / 7u;
            unsigned p  = (q == 6u) ? 84u : (20u + 21u * (q >> 1) + (q & 1u));
            int loc = (int)(85u * gg + p);
            int t = tbase + loc;

            unsigned rem0 = (unsigned)t << 2;
            unsigned r  = rem0 / 85u;
            unsigned k0 = rem0 - r * 85u;

            float4 roi = __ldg(&rois[r]);
            float4 tg  = __ldg(&regr4[(size_t)r * Cm1 + c0]);

            float gx = rintf(fmaf(roi.z, tg.x, roi.x));
            float gy = rintf(fmaf(roi.w, tg.y, roi.y));
            float gw = rintf(roi.z * expf(tg.z));
            float gh = rintf(roi.w * expf(tg.w));
            float b[4];
            b[0] = gx * invW;
            b[1] = gy * invH;
            b[2] = (gx + gw) * invW;
            b[3] = (gy + gh) * invH;

            float cv[4];                     // cls values (0 where box slot)
            float ov[4];
#pragma unroll
            for (int i = 0; i < 4; ++i) {
                int k = (int)k0 + i;
                int rr = (int)r;
                if (k >= 85) { k -= 85; ++rr; }
                if (k < 81) { cv[i] = __ldg(&cls[(size_t)rr * 81 + k]); ov[i] = cv[i]; }
                else        { cv[i] = 0.0f;  ov[i] = b[k - 81]; }
            }
            float4 o; o.x = ov[0]; o.y = ov[1]; o.z = ov[2]; o.w = ov[3];
            __stcs(&plane0[t], o);
            float4 cvv; cvv.x = cv[0]; cvv.y = cv[1]; cvv.z = cv[2]; cvv.w = cv[3];
            val[s]  = cvv;                   // stash class-invariant cls blend
            locs[s] = loc | (-2147483647 - 1);   // sign bit => boundary
        }
    }

    if (!c1ok) return;

    // ---------------- Phase 2: plane c1 (replay from registers) ----------------
#pragma unroll
    for (int s = 0; s < 3; ++s) {
        int ls = locs[s];
        if (ls >= 0) {
            // FAST replay: one streaming store, no reload
            __stcs(&plane1[tbase + ls], val[s]);
        } else {
            int loc = ls & 0x7FFFFFFF;
            if (loc == 0x7FFFFFFF) continue; // sentinel (no task)
            // loc sentinel check: sentinel was 0x80000000 -> loc 0 would collide,
            // but threadIdx.x task v>=680 only occurs for s=2 with v=tid+512>=680,
            // i.e. tid>=168, and loc 0 belongs to v=0 (tid 0, s=0) -> no collision
            // for s<2. For s=2, v=tid+512 in [512,680) -> boundary tasks have
            // loc >= 85*? ... guard via explicit no-task re-check:
            int v = threadIdx.x + s * 256;
            if (v >= 680) continue;

            int t = tbase + loc;
            unsigned rem0 = (unsigned)t << 2;
            unsigned r  = rem0 / 85u;
            unsigned k0 = rem0 - r * 85u;

            float4 roi = __ldg(&rois[r]);                       // L1/L2 hit
            float4 tg  = __ldg(&regr4[(size_t)r * Cm1 + c1]);

            float gx = rintf(fmaf(roi.z, tg.x, roi.x));
            float gy = rintf(fmaf(roi.w, tg.y, roi.y));
            float gw = rintf(roi.z * expf(tg.z));
            float gh = rintf(roi.w * expf(tg.w));
            float b[4];
            b[0] = gx * invW;
            b[1] = gy * invH;
            b[2] = (gx + gw) * invW;
            b[3] = (gy + gh) * invH;

            float cv[4] = { val[s].x, val[s].y, val[s].z, val[s].w };
            float ov[4];
#pragma unroll
            for (int i = 0; i < 4; ++i) {
                int k = (int)k0 + i;
                if (k >= 85) k -= 85;
                ov[i] = (k < 81) ? cv[i] : b[k - 81];
            }
            float4 o; o.x = ov[0]; o.y = ov[1]; o.z = ov[2]; o.w = ov[3];
            __stcs(&plane1[t], o);
        }
    }
}

// ---------------- Generic scalar fallback ----------------
__global__ void __launch_bounds__(256)
bb_generic_kernel(const float* __restrict__ regr, const float* __restrict__ cls,
                  const float4* __restrict__ rois, float* __restrict__ out,
                  int R, int Cm1, int NC, float invW, float invH, long long total)
{
    long long idx = (long long)blockIdx.x * blockDim.x + threadIdx.x;
    long long stride = (long long)gridDim.x * blockDim.x;
    const int rowlen = NC + 4;
    const long long perC = (long long)R * rowlen;
    for (; idx < total; idx += stride) {
        int c   = (int)(idx / perC);
        int rem = (int)(idx - (long long)c * perC);
        int r   = rem / rowlen;
        int k   = rem - r * rowlen;
        float val;
        if (k < NC) {
            val = cls[(long long)r * NC + k];
        } else {
            float4 roi = __ldg(&rois[r]);
            const float* rg = regr + ((long long)r * Cm1 + c) * 4;
            int comp = k - NC;
            if (comp == 0)      val = rintf(fmaf(roi.z, rg[0], roi.x)) * invW;
            else if (comp == 1) val = rintf(fmaf(roi.w, rg[1], roi.y)) * invH;
            else if (comp == 2) val = (rintf(fmaf(roi.z, rg[0], roi.x)) +
                                       rintf(roi.z * expf(rg[2]))) * invW;
            else                val = (rintf(fmaf(roi.w, rg[1], roi.y)) +
                                       rintf(roi.w * expf(rg[3]))) * invH;
        }
        out[idx] = val;
    }
}

extern "C" void kernel_launch(void* const* d_in, const int* in_sizes, int n_in,
                              void* d_out, int out_size)
{
    const float*  regr = (const float*)d_in[0];   // [1, R, 4*Cm1]
    const float*  cls  = (const float*)d_in[1];   // [1, R, NC]
    const float4* rois = (const float4*)d_in[2];  // [1, R, 4]

    const int R   = in_sizes[2] / 4;
    const int Cm1 = in_sizes[0] / (R * 4);
    const int NC  = in_sizes[1] / R;
    const int rowlen = NC + 4;

    long long hw = (long long)in_sizes[3] / 3;    // H = W = isqrt(b_elems/3)
    int side = 1;
    while ((long long)(side + 1) * (side + 1) <= hw) ++side;
    const float invW = 1.0f / (float)side;
    const float invH = 1.0f / (float)side;

    float* out = (float*)d_out;
    const long long perC  = (long long)R * rowlen;
    const long long total = (long long)out_size;

    if (rowlen == 85 && (R % 32) == 0 &&
        total == (long long)Cm1 * perC && (perC % 4) == 0) {
        const int perC4  = (int)(perC >> 2);
        const int blocksX = R / 32;               // 8 groups per block
        dim3 grid(blocksX, (Cm1 + 1) / 2);
        bb_dense2_kernel<<<grid, 256>>>(
            cls, (const float4*)cls, (const float4*)regr, rois,
            (float4*)out, perC4, R, Cm1, invW, invH);
    } else {
        long long blocks = (total + 255) / 256;
        if (blocks > 262144) blocks = 262144;
        bb_generic_kernel<<<(unsigned)blocks, 256>>>(
            regr, cls, rois, out, R, Cm1, NC, invW, invH, total);
    }
}